// round 1
// baseline (speedup 1.0000x reference)
#include <cuda_runtime.h>
#include <math_constants.h>

// Problem shape (fixed by the dataset): pred [B,M,3] f32, gt [B,N,3] f32.
constexpr int B = 4;
constexpr int M = 8192;
constexpr int N = 8192;
constexpr int TPB = 256;       // threads per block, 1 pred point per thread
constexpr int CHUNK = 2048;    // gt points per block (split-K over N)
constexpr int NCHUNK = N / CHUNK;

// Scratch (no allocation allowed -> __device__ globals).
// g_gt[b*N+n] = (-2*x, -2*y, -2*z, x^2+y^2+z^2)
__device__ float4   g_gt[B * N];
// per-pred running min of d^2 (non-negative float bits -> uint order == float order)
__device__ unsigned g_min[B * M];

__global__ void pack_gt_kernel(const float* __restrict__ gt) {
    int i = blockIdx.x * blockDim.x + threadIdx.x;
    if (i < B * N) {
        float x = gt[3 * i + 0];
        float y = gt[3 * i + 1];
        float z = gt[3 * i + 2];
        g_gt[i] = make_float4(-2.0f * x, -2.0f * y, -2.0f * z,
                              x * x + y * y + z * z);
    }
}

__global__ void init_min_kernel() {
    int i = blockIdx.x * blockDim.x + threadIdx.x;
    if (i < B * M) g_min[i] = 0x7F800000u;  // +inf
}

// grid: (M/TPB, B, NCHUNK), block: TPB
__global__ __launch_bounds__(TPB) void min_dist_kernel(const float* __restrict__ pred) {
    __shared__ float4 tile[CHUNK];  // 32 KB

    const int b     = blockIdx.y;
    const int m     = blockIdx.x * TPB + threadIdx.x;
    const int chunk = blockIdx.z;

    // Cooperative load of this block's gt chunk into smem (coalesced float4).
    const float4* __restrict__ gsrc = g_gt + b * N + chunk * CHUNK;
    #pragma unroll
    for (int j = threadIdx.x; j < CHUNK; j += TPB) tile[j] = gsrc[j];

    // This thread's pred point.
    const int pbase = (b * M + m) * 3;
    const float px = pred[pbase + 0];
    const float py = pred[pbase + 1];
    const float pz = pred[pbase + 2];

    __syncthreads();

    // 8 independent min accumulators to break the FMNMX dependency chain.
    float acc0 = CUDART_INF_F, acc1 = CUDART_INF_F, acc2 = CUDART_INF_F, acc3 = CUDART_INF_F;
    float acc4 = CUDART_INF_F, acc5 = CUDART_INF_F, acc6 = CUDART_INF_F, acc7 = CUDART_INF_F;

    #pragma unroll 4
    for (int j = 0; j < CHUNK; j += 8) {
        float4 g0 = tile[j + 0];
        float4 g1 = tile[j + 1];
        float4 g2 = tile[j + 2];
        float4 g3 = tile[j + 3];
        float4 g4 = tile[j + 4];
        float4 g5 = tile[j + 5];
        float4 g6 = tile[j + 6];
        float4 g7 = tile[j + 7];
        // s = ||g||^2 - 2*(p.g)   (= d^2 - ||p||^2, min-equivalent to d^2)
        float s0 = fmaf(px, g0.x, fmaf(py, g0.y, fmaf(pz, g0.z, g0.w)));
        float s1 = fmaf(px, g1.x, fmaf(py, g1.y, fmaf(pz, g1.z, g1.w)));
        float s2 = fmaf(px, g2.x, fmaf(py, g2.y, fmaf(pz, g2.z, g2.w)));
        float s3 = fmaf(px, g3.x, fmaf(py, g3.y, fmaf(pz, g3.z, g3.w)));
        float s4 = fmaf(px, g4.x, fmaf(py, g4.y, fmaf(pz, g4.z, g4.w)));
        float s5 = fmaf(px, g5.x, fmaf(py, g5.y, fmaf(pz, g5.z, g5.w)));
        float s6 = fmaf(px, g6.x, fmaf(py, g6.y, fmaf(pz, g6.z, g6.w)));
        float s7 = fmaf(px, g7.x, fmaf(py, g7.y, fmaf(pz, g7.z, g7.w)));
        acc0 = fminf(acc0, s0);
        acc1 = fminf(acc1, s1);
        acc2 = fminf(acc2, s2);
        acc3 = fminf(acc3, s3);
        acc4 = fminf(acc4, s4);
        acc5 = fminf(acc5, s5);
        acc6 = fminf(acc6, s6);
        acc7 = fminf(acc7, s7);
    }

    float smin = fminf(fminf(fminf(acc0, acc1), fminf(acc2, acc3)),
                       fminf(fminf(acc4, acc5), fminf(acc6, acc7)));

    // Partial d^2 for this gt chunk; clamp is monotone so it commutes with
    // the min across chunks.
    const float a2 = fmaf(px, px, fmaf(py, py, pz * pz));
    float d2 = fmaxf(a2 + smin, 0.0f);

    // Non-negative floats: uint compare == float compare.
    atomicMin(&g_min[b * M + m], __float_as_uint(d2));
}

// Single block, deterministic tree reduction: mean of sqrt(min d^2).
__global__ void reduce_kernel(float* __restrict__ out, int out_size) {
    __shared__ float ssum[1024];
    float sum = 0.0f;
    for (int i = threadIdx.x; i < B * M; i += 1024)
        sum += sqrtf(__uint_as_float(g_min[i]));
    ssum[threadIdx.x] = sum;
    __syncthreads();
    for (int s = 512; s > 0; s >>= 1) {
        if (threadIdx.x < s) ssum[threadIdx.x] += ssum[threadIdx.x + s];
        __syncthreads();
    }
    float val = ssum[0] * (1.0f / (float)(B * M));  // LOSS_WEIGHT = 1.0
    for (int i = threadIdx.x; i < out_size; i += 1024) out[i] = val;
}

extern "C" void kernel_launch(void* const* d_in, const int* in_sizes, int n_in,
                              void* d_out, int out_size) {
    const float* pred = (const float*)d_in[0];  // [B, M, 3]
    const float* gt   = (const float*)d_in[1];  // [B, N, 3]
    float* out = (float*)d_out;

    pack_gt_kernel<<<(B * N + 255) / 256, 256>>>(gt);
    init_min_kernel<<<(B * M + 255) / 256, 256>>>();

    dim3 grid(M / TPB, B, NCHUNK);
    min_dist_kernel<<<grid, TPB>>>(pred);

    reduce_kernel<<<1, 1024>>>(out, out_size);
}

// round 3
// speedup vs baseline: 1.4481x; 1.4481x over previous
#include <cuda_runtime.h>
#include <math_constants.h>

// Shape fixed by dataset: pred [B,M,3] f32, gt [B,N,3] f32.
constexpr int B = 4;
constexpr int M = 8192;
constexpr int N = 8192;

constexpr int TPB   = 256;   // threads per block in main kernel
constexpr int P     = 8;     // pred points per thread (4 f32x2 pairs)
constexpr int CHUNK = 512;   // gt points per block (split-K over N)
constexpr int NCHUNK = N / CHUNK;            // 16
constexpr int MBLK  = M / (TPB * P);         // 4 blocks along M

constexpr int REDB = 32;     // reduction partial blocks

// Scratch (__device__ globals; no allocation allowed).
// Duplicated-packed gt: per point i, two float4:
//   g_gt2[2i]   = (-2x, -2x, -2y, -2y)
//   g_gt2[2i+1] = (-2z, -2z,  b2,  b2)   with b2 = x^2+y^2+z^2
__device__ float4   g_gt2[2 * B * N];
__device__ unsigned g_min[B * M];       // running min of d^2 (float bits)
__device__ float    g_partial[REDB];

// ---------------- f32x2 helpers (sm_103a packed fp32) ----------------
__device__ __forceinline__ unsigned long long pack2(float lo, float hi) {
    unsigned long long r;
    asm("mov.b64 %0, {%1, %2};" : "=l"(r) : "f"(lo), "f"(hi));
    return r;
}
__device__ __forceinline__ void unpack2(unsigned long long v, float& lo, float& hi) {
    asm("mov.b64 {%0, %1}, %2;" : "=f"(lo), "=f"(hi) : "l"(v));
}
__device__ __forceinline__ unsigned long long fma2(unsigned long long a,
                                                   unsigned long long b,
                                                   unsigned long long c) {
    unsigned long long d;
    asm("fma.rn.f32x2 %0, %1, %2, %3;" : "=l"(d) : "l"(a), "l"(b), "l"(c));
    return d;
}

// ---------------- prep kernels ----------------
__global__ void pack_gt_kernel(const float* __restrict__ gt) {
    int i = blockIdx.x * blockDim.x + threadIdx.x;
    if (i < B * N) {
        float x = gt[3 * i + 0];
        float y = gt[3 * i + 1];
        float z = gt[3 * i + 2];
        float b2 = x * x + y * y + z * z;
        g_gt2[2 * i]     = make_float4(-2.0f * x, -2.0f * x, -2.0f * y, -2.0f * y);
        g_gt2[2 * i + 1] = make_float4(-2.0f * z, -2.0f * z, b2, b2);
    }
}

__global__ void init_min_kernel() {
    int i = blockIdx.x * blockDim.x + threadIdx.x;
    if (i < B * M) g_min[i] = 0x7F800000u;  // +inf
}

// ---------------- main kernel ----------------
// grid: (MBLK, B, NCHUNK), block: TPB. Each thread: P preds vs CHUNK gts.
__global__ __launch_bounds__(TPB) void min_dist_kernel(const float* __restrict__ pred) {
    __shared__ float4 tile[2 * CHUNK];  // 16 KB, duplicated-packed gt chunk

    const int b     = blockIdx.y;
    const int chunk = blockIdx.z;

    // Cooperative coalesced load of the gt chunk (1024 float4 / 256 thr).
    const float4* __restrict__ gsrc = g_gt2 + 2 * (b * N + chunk * CHUNK);
    #pragma unroll
    for (int j = threadIdx.x; j < 2 * CHUNK; j += TPB) tile[j] = gsrc[j];

    // This thread's P pred points (strided by TPB within the block's span).
    const int mbase = blockIdx.x * (TPB * P) + threadIdx.x;
    unsigned long long ppx[P / 2], ppy[P / 2], ppz[P / 2];
    #pragma unroll
    for (int k = 0; k < P / 2; k++) {
        int m0 = mbase + (2 * k)     * TPB;
        int m1 = mbase + (2 * k + 1) * TPB;
        const float* p0 = pred + (b * M + m0) * 3;
        const float* p1 = pred + (b * M + m1) * 3;
        ppx[k] = pack2(p0[0], p1[0]);
        ppy[k] = pack2(p0[1], p1[1]);
        ppz[k] = pack2(p0[2], p1[2]);
    }

    __syncthreads();

    float acc[P];
    #pragma unroll
    for (int k = 0; k < P; k++) acc[k] = CUDART_INF_F;

    const ulonglong2* __restrict__ t2 = reinterpret_cast<const ulonglong2*>(tile);

    #pragma unroll 4
    for (int j = 0; j < CHUNK; j++) {
        ulonglong2 ga = t2[2 * j];      // (gx2, gy2)
        ulonglong2 gb = t2[2 * j + 1];  // (gz2, gw2)
        #pragma unroll
        for (int k = 0; k < P / 2; k++) {
            // s = b2 - 2*(p.g)   (== d^2 - ||p||^2; min-equivalent)
            unsigned long long s2 =
                fma2(ppx[k], ga.x, fma2(ppy[k], ga.y, fma2(ppz[k], gb.x, gb.y)));
            float slo, shi;
            unpack2(s2, slo, shi);
            acc[2 * k]     = fminf(acc[2 * k],     slo);
            acc[2 * k + 1] = fminf(acc[2 * k + 1], shi);
        }
    }

    // Epilogue: add ||p||^2, clamp, merge across chunks via atomicMin on bits.
    #pragma unroll
    for (int k = 0; k < P / 2; k++) {
        float x0, x1, y0, y1, z0, z1;
        unpack2(ppx[k], x0, x1);
        unpack2(ppy[k], y0, y1);
        unpack2(ppz[k], z0, z1);
        float a20 = fmaf(x0, x0, fmaf(y0, y0, z0 * z0));
        float a21 = fmaf(x1, x1, fmaf(y1, y1, z1 * z1));
        float d20 = fmaxf(a20 + acc[2 * k], 0.0f);
        float d21 = fmaxf(a21 + acc[2 * k + 1], 0.0f);
        int m0 = mbase + (2 * k)     * TPB;
        int m1 = mbase + (2 * k + 1) * TPB;
        atomicMin(&g_min[b * M + m0], __float_as_uint(d20));
        atomicMin(&g_min[b * M + m1], __float_as_uint(d21));
    }
}

// ---------------- deterministic two-stage reduction ----------------
__global__ void reduce_partial_kernel() {
    __shared__ float ssum[1024];
    const int tid = threadIdx.x;
    int i = blockIdx.x * 1024 + tid;
    float sum = sqrtf(__uint_as_float(g_min[i]));   // 32 blocks * 1024 = 32768 exactly
    ssum[tid] = sum;
    __syncthreads();
    for (int s = 512; s > 0; s >>= 1) {
        if (tid < s) ssum[tid] += ssum[tid + s];
        __syncthreads();
    }
    if (tid == 0) g_partial[blockIdx.x] = ssum[0];
}

__global__ void reduce_final_kernel(float* __restrict__ out, int out_size) {
    float sum = 0.0f;
    #pragma unroll
    for (int i = 0; i < REDB; i++) sum += g_partial[i];
    float val = sum * (1.0f / (float)(B * M));  // LOSS_WEIGHT = 1.0
    for (int i = threadIdx.x; i < out_size; i += 32) out[i] = val;
}

extern "C" void kernel_launch(void* const* d_in, const int* in_sizes, int n_in,
                              void* d_out, int out_size) {
    const float* pred = (const float*)d_in[0];  // [B, M, 3]
    const float* gt   = (const float*)d_in[1];  // [B, N, 3]
    float* out = (float*)d_out;

    pack_gt_kernel<<<(B * N + 255) / 256, 256>>>(gt);
    init_min_kernel<<<(B * M + 255) / 256, 256>>>();

    dim3 grid(MBLK, B, NCHUNK);  // 4 x 4 x 16 = 256 blocks
    min_dist_kernel<<<grid, TPB>>>(pred);

    reduce_partial_kernel<<<REDB, 1024>>>();
    reduce_final_kernel<<<1, 32>>>(out, out_size);
}